// round 1
// baseline (speedup 1.0000x reference)
#include <cuda_runtime.h>
#include <cstdint>

#define EPSV 1e-7f

// Scratch (no cudaMalloc allowed): M[s][c][i][a] and rowsum[s][c][i]
__device__ float g_M[16 * 4 * 1024 * 128];   // 33.5 MB
__device__ float g_rowsum[16 * 4 * 1024];

__device__ __forceinline__ uint32_t f2tf(float f) {
    uint32_t r;
    asm("cvt.rna.tf32.f32 %0, %1;" : "=r"(r) : "f"(f));
    return r;
}

__device__ __forceinline__ void mma8(float acc[4], const uint32_t a[4], const uint32_t b[2]) {
    asm volatile(
        "mma.sync.aligned.m16n8k8.row.col.f32.tf32.tf32.f32 "
        "{%0,%1,%2,%3}, {%4,%5,%6,%7}, {%8,%9}, {%0,%1,%2,%3};\n"
        : "+f"(acc[0]), "+f"(acc[1]), "+f"(acc[2]), "+f"(acc[3])
        : "r"(a[0]), "r"(a[1]), "r"(a[2]), "r"(a[3]), "r"(b[0]), "r"(b[1]));
}

// ---------------------------------------------------------------------------
// Kernel 1: per (s, 32-row i-tile): LHS rows = (c*32 + il), 128x128x1024 GEMM
// M_c = Ar_c @ x, plus fused rowsum of Ar over j.
// ---------------------------------------------------------------------------
#define LDA1 68
#define LDB1 136
#define SMEM1 ((128 * LDA1 + 64 * LDB1) * 4 + 256 * 4)

__global__ void __launch_bounds__(256, 2)
k1_gemm(const float* __restrict__ A, const float* __restrict__ x)
{
    extern __shared__ uint32_t sm1[];
    uint32_t* As = sm1;                       // [128][LDA1] tf32, row = c*32+il, col = j
    uint32_t* Xs = sm1 + 128 * LDA1;          // [64][LDB1]  tf32, [j][a]
    float* rs_sm = (float*)(Xs + 64 * LDB1);  // [256]

    const int tid = threadIdx.x;
    const int s = blockIdx.y;
    const int i0 = blockIdx.x * 32;
    const int warp = tid >> 5, lane = tid & 31;
    const int wm = warp & 1, wn = warp >> 1;
    const int grp = lane >> 2, tig = lane & 3;

    float acc[4][4][4];
#pragma unroll
    for (int mi = 0; mi < 4; mi++)
#pragma unroll
        for (int ni = 0; ni < 4; ni++)
#pragma unroll
            for (int e = 0; e < 4; e++) acc[mi][ni][e] = 0.f;

    float rs_acc = 0.f;
    const int rs_row = tid & 127;
    const int rs_c0 = (tid >> 7) * 32;

    const float* Abase = A + (size_t)(s * 1024 + i0) * (1024 * 5);
    const float* Xbase = x + (size_t)s * (1024 * 128);

    for (int kt = 0; kt < 16; kt++) {
        // ---- load A tile: 32 rows x (64 j x 5 c), keep c<4, tf32-convert ----
        const float* At = Abase + (size_t)kt * (64 * 5);
#pragma unroll
        for (int it = 0; it < 10; it++) {
            int f = tid + it * 256;           // < 2560
            int il = f / 80;
            int q = f - il * 80;
            float4 v = *reinterpret_cast<const float4*>(At + (size_t)il * 5120 + q * 4);
            int p = q * 4;
            float vv[4] = {v.x, v.y, v.z, v.w};
#pragma unroll
            for (int e = 0; e < 4; e++) {
                int pe = p + e;
                int jj = pe / 5;
                int c = pe - jj * 5;
                if (c < 4) As[(c * 32 + il) * LDA1 + jj] = f2tf(vv[e]);
            }
        }
        // ---- load x tile: 64 x 128 contiguous ----
        const float* Xt = Xbase + (size_t)kt * (64 * 128);
#pragma unroll
        for (int it = 0; it < 8; it++) {
            int f = tid + it * 256;           // < 2048
            float4 v = reinterpret_cast<const float4*>(Xt)[f];
            int jj = f >> 5;
            int a = (f & 31) * 4;
            uint32_t* d = &Xs[jj * LDB1 + a];
            d[0] = f2tf(v.x); d[1] = f2tf(v.y); d[2] = f2tf(v.z); d[3] = f2tf(v.w);
        }
        __syncthreads();

        // fused rowsum (2 threads per row, 32 cols each)
#pragma unroll
        for (int j = 0; j < 32; j++)
            rs_acc += __uint_as_float(As[rs_row * LDA1 + rs_c0 + j]);

        // ---- 8 k8-steps of m16n8k8 tf32 ----
#pragma unroll
        for (int kk = 0; kk < 8; kk++) {
            const int kc = kk * 8;
            uint32_t af[4][4], bf[4][2];
#pragma unroll
            for (int mi = 0; mi < 4; mi++) {
                int r = wm * 64 + mi * 16 + grp;
                af[mi][0] = As[r * LDA1 + kc + tig];
                af[mi][1] = As[(r + 8) * LDA1 + kc + tig];
                af[mi][2] = As[r * LDA1 + kc + tig + 4];
                af[mi][3] = As[(r + 8) * LDA1 + kc + tig + 4];
            }
#pragma unroll
            for (int ni = 0; ni < 4; ni++) {
                int cn = wn * 32 + ni * 8 + grp;
                bf[ni][0] = Xs[(kc + tig) * LDB1 + cn];
                bf[ni][1] = Xs[(kc + tig + 4) * LDB1 + cn];
            }
#pragma unroll
            for (int mi = 0; mi < 4; mi++)
#pragma unroll
                for (int ni = 0; ni < 4; ni++)
                    mma8(acc[mi][ni], af[mi], bf[ni]);
        }
        __syncthreads();
    }

    // ---- rowsum writeback ----
    rs_sm[tid] = rs_acc;
    __syncthreads();
    if (tid < 128) {
        int c = tid >> 5, il = tid & 31;
        g_rowsum[(s * 4 + c) * 1024 + i0 + il] = rs_sm[tid] + rs_sm[tid + 128];
    }

    // ---- M writeback: rows decode as (c, il) ----
#pragma unroll
    for (int mi = 0; mi < 4; mi++) {
#pragma unroll
        for (int ni = 0; ni < 4; ni++) {
            int cn = wn * 32 + ni * 8 + tig * 2;
            int r0 = wm * 64 + mi * 16 + grp;
            int c0 = r0 >> 5, il0 = r0 & 31;
            *reinterpret_cast<float2*>(
                &g_M[((size_t)(s * 4 + c0) * 1024 + i0 + il0) * 128 + cn]) =
                make_float2(acc[mi][ni][0], acc[mi][ni][1]);
            int r1 = r0 + 8;
            int c1 = r1 >> 5, il1 = r1 & 31;
            *reinterpret_cast<float2*>(
                &g_M[((size_t)(s * 4 + c1) * 1024 + i0 + il1) * 128 + cn]) =
                make_float2(acc[mi][ni][2], acc[mi][ni][3]);
        }
    }
}

// ---------------------------------------------------------------------------
// Kernel 2: out = tanh( sum_c (norm_c ⊙ M_c) @ W_c  +  x @ theta )
// One 128x128x(5*128) GEMM per (s, 128-row i-tile).
// ---------------------------------------------------------------------------
#define LDA2 132
#define LDB2 136
#define SMEM2 ((512 + 128 * LDA2 + 128 * LDB2) * 4)

__global__ void __launch_bounds__(256, 1)
k2_agg(const float* __restrict__ x, const float* __restrict__ weight,
       const float* __restrict__ theta, float* __restrict__ out)
{
    extern __shared__ uint32_t sm2[];
    float* nrm = (float*)sm2;                 // [4][128]
    uint32_t* Ls = sm2 + 512;                 // [128][LDA2]  (i x k)
    uint32_t* Ws = Ls + 128 * LDA2;           // [128][LDB2]  (k x b)

    const int tid = threadIdx.x;
    const int s = blockIdx.y;
    const int i0 = blockIdx.x * 128;
    const int warp = tid >> 5, lane = tid & 31;
    const int wm = warp & 1, wn = warp >> 1;
    const int grp = lane >> 2, tig = lane & 3;

#pragma unroll
    for (int it = 0; it < 2; it++) {
        int f = tid + it * 256;
        int c = f >> 7, i = f & 127;
        nrm[f] = 1.0f / (g_rowsum[(s * 4 + c) * 1024 + i0 + i] + EPSV);
    }

    float acc[4][4][4];
#pragma unroll
    for (int mi = 0; mi < 4; mi++)
#pragma unroll
        for (int ni = 0; ni < 4; ni++)
#pragma unroll
            for (int e = 0; e < 4; e++) acc[mi][ni][e] = 0.f;

    for (int cc = 0; cc < 5; cc++) {
        __syncthreads();  // nrm ready (cc=0) / previous mma done before smem overwrite
        if (cc < 4) {
            const float* Mp = &g_M[((size_t)(s * 4 + cc) * 1024 + i0) * 128];
#pragma unroll
            for (int it = 0; it < 16; it++) {
                int f = tid + it * 256;       // < 4096
                int il = f >> 5;
                int a = (f & 31) * 4;
                float4 v = reinterpret_cast<const float4*>(Mp)[f];
                float nm = nrm[cc * 128 + il];
                uint32_t* d = &Ls[il * LDA2 + a];
                d[0] = f2tf(v.x * nm); d[1] = f2tf(v.y * nm);
                d[2] = f2tf(v.z * nm); d[3] = f2tf(v.w * nm);
            }
#pragma unroll
            for (int it = 0; it < 64; it++) {
                int f = tid + it * 256;       // < 16384
                int a = f >> 7, b = f & 127;
                Ws[a * LDB2 + b] = f2tf(weight[(a * 128 + b) * 4 + cc]);
            }
        } else {
            const float* Xp = x + (size_t)(s * 1024 + i0) * 128;
#pragma unroll
            for (int it = 0; it < 16; it++) {
                int f = tid + it * 256;
                int il = f >> 5;
                int a = (f & 31) * 4;
                float4 v = reinterpret_cast<const float4*>(Xp)[f];
                uint32_t* d = &Ls[il * LDA2 + a];
                d[0] = f2tf(v.x); d[1] = f2tf(v.y); d[2] = f2tf(v.z); d[3] = f2tf(v.w);
            }
#pragma unroll
            for (int it = 0; it < 16; it++) {
                int f = tid + it * 256;
                int a = f >> 5;
                int b = (f & 31) * 4;
                float4 v = reinterpret_cast<const float4*>(theta)[f];
                uint32_t* d = &Ws[a * LDB2 + b];
                d[0] = f2tf(v.x); d[1] = f2tf(v.y); d[2] = f2tf(v.z); d[3] = f2tf(v.w);
            }
        }
        __syncthreads();

#pragma unroll
        for (int kk = 0; kk < 16; kk++) {
            const int kc = kk * 8;
            uint32_t af[4][4], bf[4][2];
#pragma unroll
            for (int mi = 0; mi < 4; mi++) {
                int r = wm * 64 + mi * 16 + grp;
                af[mi][0] = Ls[r * LDA2 + kc + tig];
                af[mi][1] = Ls[(r + 8) * LDA2 + kc + tig];
                af[mi][2] = Ls[r * LDA2 + kc + tig + 4];
                af[mi][3] = Ls[(r + 8) * LDA2 + kc + tig + 4];
            }
#pragma unroll
            for (int ni = 0; ni < 4; ni++) {
                int cn = wn * 32 + ni * 8 + grp;
                bf[ni][0] = Ws[(kc + tig) * LDB2 + cn];
                bf[ni][1] = Ws[(kc + tig + 4) * LDB2 + cn];
            }
#pragma unroll
            for (int mi = 0; mi < 4; mi++)
#pragma unroll
                for (int ni = 0; ni < 4; ni++)
                    mma8(acc[mi][ni], af[mi], bf[ni]);
        }
    }

    // ---- epilogue: tanh + store ----
#pragma unroll
    for (int mi = 0; mi < 4; mi++) {
#pragma unroll
        for (int ni = 0; ni < 4; ni++) {
            int cn = wn * 32 + ni * 8 + tig * 2;
            int r0 = wm * 64 + mi * 16 + grp;
            *reinterpret_cast<float2*>(&out[((size_t)(s * 1024) + i0 + r0) * 128 + cn]) =
                make_float2(tanhf(acc[mi][ni][0]), tanhf(acc[mi][ni][1]));
            int r1 = r0 + 8;
            *reinterpret_cast<float2*>(&out[((size_t)(s * 1024) + i0 + r1) * 128 + cn]) =
                make_float2(tanhf(acc[mi][ni][2]), tanhf(acc[mi][ni][3]));
        }
    }
}

// ---------------------------------------------------------------------------
extern "C" void kernel_launch(void* const* d_in, const int* in_sizes, int n_in,
                              void* d_out, int out_size)
{
    const float* A     = (const float*)d_in[0];
    const float* x     = (const float*)d_in[1];
    const float* w     = (const float*)d_in[2];
    const float* theta = (const float*)d_in[3];
    float* out = (float*)d_out;

    cudaFuncSetAttribute(k1_gemm, cudaFuncAttributeMaxDynamicSharedMemorySize, SMEM1);
    cudaFuncSetAttribute(k2_agg,  cudaFuncAttributeMaxDynamicSharedMemorySize, SMEM2);

    k1_gemm<<<dim3(32, 16), 256, SMEM1>>>(A, x);
    k2_agg<<<dim3(8, 16), 256, SMEM2>>>(x, w, theta, out);
}

// round 2
// speedup vs baseline: 1.2430x; 1.2430x over previous
#include <cuda_runtime.h>
#include <cstdint>

#define EPSV 1e-7f

// Scratch (no cudaMalloc allowed)
__device__ float g_M[16 * 4 * 1024 * 128];   // normalized m, [s][c][i][a], 33.5 MB
__device__ float g_Wt[5 * 128 * 128];        // [c][a][b], c=4 slot = theta

__device__ __forceinline__ uint32_t f2tf(float f) {
    uint32_t r;
    asm("cvt.rna.tf32.f32 %0, %1;" : "=r"(r) : "f"(f));
    return r;
}
__device__ __forceinline__ float fasttanh(float x) {
    float y;
    asm("tanh.approx.f32 %0, %1;" : "=f"(y) : "f"(x));
    return y;
}
__device__ __forceinline__ void mma8(float acc[4], const uint32_t a[4], const uint32_t b[2]) {
    asm volatile(
        "mma.sync.aligned.m16n8k8.row.col.f32.tf32.tf32.f32 "
        "{%0,%1,%2,%3}, {%4,%5,%6,%7}, {%8,%9}, {%0,%1,%2,%3};\n"
        : "+f"(acc[0]), "+f"(acc[1]), "+f"(acc[2]), "+f"(acc[3])
        : "r"(a[0]), "r"(a[1]), "r"(a[2]), "r"(a[3]), "r"(b[0]), "r"(b[1]));
}
__device__ __forceinline__ void cpa16(uint32_t saddr, const void* g) {
    asm volatile("cp.async.cg.shared.global [%0], [%1], 16;" :: "r"(saddr), "l"(g));
}
#define CP_COMMIT asm volatile("cp.async.commit_group;")
#define CP_WAIT0  asm volatile("cp.async.wait_group 0;")

// ---------------------------------------------------------------------------
// k0: transpose weight[a][b][c] (c fastest) -> g_Wt[c][a][b]; c=4 = theta.
// ---------------------------------------------------------------------------
__global__ void k0_wt(const float* __restrict__ w, const float* __restrict__ th) {
    int o = blockIdx.x * 256 + threadIdx.x;     // < 81920
    int c = o >> 14, ab = o & 16383;
    g_Wt[o] = (c < 4) ? w[ab * 4 + c] : th[ab];
}

// ---------------------------------------------------------------------------
// k1: per (s, 32 i-rows): LHS rows = (c*32+il), 128x128x1024 tf32 GEMM,
//     fused rowsum -> norm folded into epilogue. 2-stage pipeline.
// ---------------------------------------------------------------------------
#define LDA1 68
#define LDB1 136
#define K1_ASZ (128 * LDA1)
#define K1_XSZ (64 * LDB1)
#define SMEM1 ((2 * K1_ASZ + 2 * K1_XSZ + 256) * 4)

__global__ void __launch_bounds__(256, 1)
k1_gemm(const float* __restrict__ A, const float* __restrict__ x)
{
    extern __shared__ float smem[];
    float* Asb[2] = { smem, smem + K1_ASZ };
    float* Xsb[2] = { smem + 2 * K1_ASZ, smem + 2 * K1_ASZ + K1_XSZ };
    float* rs_sm  = smem + 2 * K1_ASZ + 2 * K1_XSZ;

    const int tid = threadIdx.x;
    const int s = blockIdx.y, i0 = blockIdx.x * 32;
    const int warp = tid >> 5, lane = tid & 31;
    const int wm = warp & 1, wn = warp >> 1;
    const int grp = lane >> 2, tig = lane & 3;

    uint32_t xs_u32[2];
    xs_u32[0] = (uint32_t)__cvta_generic_to_shared(Xsb[0]);
    xs_u32[1] = (uint32_t)__cvta_generic_to_shared(Xsb[1]);

    // precomputed A-load offsets / decode packs (thread-invariant across tiles)
    int aoff[10], apack[10];
#pragma unroll
    for (int it = 0; it < 10; it++) {
        int f = tid + it * 256;
        int il = f / 80, q = f - il * 80;
        aoff[it]  = il * 5120 + q * 4;
        apack[it] = (il << 8) | q;
    }

    const float* Ab = A + (size_t)(s * 1024 + i0) * 5120;
    const float* Xb = x + (size_t)s * 131072;

    float4 areg[10];
    auto ldA = [&](int kt) {
        const float* At = Ab + kt * 320;
#pragma unroll
        for (int it = 0; it < 10; it++)
            areg[it] = *reinterpret_cast<const float4*>(At + aoff[it]);
    };
    auto stsA = [&](int pb) {
        float* dst = Asb[pb];
#pragma unroll
        for (int it = 0; it < 10; it++) {
            int il = apack[it] >> 8, q = apack[it] & 255;
            float v[4] = { areg[it].x, areg[it].y, areg[it].z, areg[it].w };
#pragma unroll
            for (int e = 0; e < 4; e++) {
                int pe = q * 4 + e;
                int j = pe / 5;
                int c = pe - j * 5;
                if (c < 4)
                    dst[(c * 32 + il) * LDA1 + j] = __uint_as_float(f2tf(v[e]));
            }
        }
    };
    auto ldX = [&](int kt, int pb) {
        const float* Xt = Xb + kt * 8192;
        uint32_t db = xs_u32[pb];
#pragma unroll
        for (int it = 0; it < 8; it++) {
            int f = tid + it * 256;
            cpa16(db + (uint32_t)(((f >> 5) * LDB1 + (f & 31) * 4) * 4), Xt + f * 4);
        }
    };

    float acc[4][4][4];
#pragma unroll
    for (int mi = 0; mi < 4; mi++)
#pragma unroll
        for (int ni = 0; ni < 4; ni++)
#pragma unroll
            for (int e = 0; e < 4; e++) acc[mi][ni][e] = 0.f;
    float rs = 0.f;

    // prologue: tile 0
    ldA(0); ldX(0, 0); CP_COMMIT;
    stsA(0);
    CP_WAIT0;
    __syncthreads();

    int p = 0;
    for (int kt = 0; kt < 16; kt++) {
        if (kt < 15) { ldA(kt + 1); ldX(kt + 1, p ^ 1); CP_COMMIT; }

        // fused rowsum (vectorized on deinterleaved tile)
        {
            const float4* rp = reinterpret_cast<const float4*>(
                Asb[p] + (tid & 127) * LDA1 + (tid >> 7) * 32);
#pragma unroll
            for (int q = 0; q < 8; q++) {
                float4 v = rp[q];
                rs += (v.x + v.y) + (v.z + v.w);
            }
        }

        const float* As = Asb[p];
        const float* Xs = Xsb[p];
#pragma unroll
        for (int kk = 0; kk < 8; kk++) {
            const int kc = kk * 8;
            uint32_t af[4][4], bf[4][2];
#pragma unroll
            for (int mi = 0; mi < 4; mi++) {
                int r = wm * 64 + mi * 16 + grp;
                af[mi][0] = __float_as_uint(As[r * LDA1 + kc + tig]);
                af[mi][1] = __float_as_uint(As[(r + 8) * LDA1 + kc + tig]);
                af[mi][2] = __float_as_uint(As[r * LDA1 + kc + tig + 4]);
                af[mi][3] = __float_as_uint(As[(r + 8) * LDA1 + kc + tig + 4]);
            }
#pragma unroll
            for (int ni = 0; ni < 4; ni++) {
                int cn = wn * 32 + ni * 8 + grp;
                bf[ni][0] = f2tf(Xs[(kc + tig) * LDB1 + cn]);
                bf[ni][1] = f2tf(Xs[(kc + tig + 4) * LDB1 + cn]);
            }
#pragma unroll
            for (int mi = 0; mi < 4; mi++)
#pragma unroll
                for (int ni = 0; ni < 4; ni++)
                    mma8(acc[mi][ni], af[mi], bf[ni]);
        }

        if (kt < 15) stsA(p ^ 1);
        CP_WAIT0;
        __syncthreads();
        p ^= 1;
    }

    // norm = 1/(rowsum + eps)
    rs_sm[tid] = rs;
    __syncthreads();
    if (tid < 128)
        rs_sm[tid] = 1.0f / (rs_sm[tid] + rs_sm[tid + 128] + EPSV);
    __syncthreads();

    // writeback normalized M
#pragma unroll
    for (int mi = 0; mi < 4; mi++) {
        int r0 = wm * 64 + mi * 16 + grp;
        int r1 = r0 + 8;
        float nm0 = rs_sm[r0], nm1 = rs_sm[r1];
        int c0 = r0 >> 5, il0 = r0 & 31;
        int c1 = r1 >> 5, il1 = r1 & 31;
        float* d0 = &g_M[((size_t)(s * 4 + c0) * 1024 + i0 + il0) * 128];
        float* d1 = &g_M[((size_t)(s * 4 + c1) * 1024 + i0 + il1) * 128];
#pragma unroll
        for (int ni = 0; ni < 4; ni++) {
            int cn = wn * 32 + ni * 8 + tig * 2;
            *reinterpret_cast<float2*>(d0 + cn) =
                make_float2(acc[mi][ni][0] * nm0, acc[mi][ni][1] * nm0);
            *reinterpret_cast<float2*>(d1 + cn) =
                make_float2(acc[mi][ni][2] * nm1, acc[mi][ni][3] * nm1);
        }
    }
}

// ---------------------------------------------------------------------------
// k2: out = tanh( [Mn_0..Mn_3, x] @ [Wt_0..Wt_3, theta] ), k = 640 in ten
//     64-wide chunks, fully cp.async double-buffered.
// ---------------------------------------------------------------------------
#define LDL2 68
#define LDW2 136
#define K2_LSZ (128 * LDL2)
#define K2_WSZ (64 * LDW2)
#define SMEM2 ((2 * K2_LSZ + 2 * K2_WSZ) * 4)

__global__ void __launch_bounds__(256, 1)
k2_agg(const float* __restrict__ x, float* __restrict__ out)
{
    extern __shared__ float smem[];
    float* Lsb[2] = { smem, smem + K2_LSZ };
    float* Wsb[2] = { smem + 2 * K2_LSZ, smem + 2 * K2_LSZ + K2_WSZ };

    const int tid = threadIdx.x;
    const int s = blockIdx.y, i0 = blockIdx.x * 128;
    const int warp = tid >> 5, lane = tid & 31;
    const int wm = warp & 1, wn = warp >> 1;
    const int grp = lane >> 2, tig = lane & 3;

    uint32_t ls_u32[2], ws_u32[2];
    ls_u32[0] = (uint32_t)__cvta_generic_to_shared(Lsb[0]);
    ls_u32[1] = (uint32_t)__cvta_generic_to_shared(Lsb[1]);
    ws_u32[0] = (uint32_t)__cvta_generic_to_shared(Wsb[0]);
    ws_u32[1] = (uint32_t)__cvta_generic_to_shared(Wsb[1]);

    auto ldChunk = [&](int cc, int pb) {
        int c = cc >> 1, half = cc & 1;
        const float* Lsrc = (c < 4)
            ? (g_M + ((size_t)(s * 4 + c) * 1024 + i0) * 128 + half * 64)
            : (x + (size_t)(s * 1024 + i0) * 128 + half * 64);
        const float* Wsrc = g_Wt + c * 16384 + half * 8192;
        uint32_t ld = ls_u32[pb], wd = ws_u32[pb];
#pragma unroll
        for (int it = 0; it < 8; it++) {          // L: 128 rows x 16 float4
            int f = tid + it * 256;
            int row = f >> 4, c4 = f & 15;
            cpa16(ld + (uint32_t)((row * LDL2 + c4 * 4) * 4), Lsrc + row * 128 + c4 * 4);
        }
#pragma unroll
        for (int it = 0; it < 8; it++) {          // W: 64 rows x 32 float4 (contig)
            int f = tid + it * 256;
            int row = f >> 5, c4 = f & 31;
            cpa16(wd + (uint32_t)((row * LDW2 + c4 * 4) * 4), Wsrc + f * 4);
        }
    };

    float acc[4][4][4];
#pragma unroll
    for (int mi = 0; mi < 4; mi++)
#pragma unroll
        for (int ni = 0; ni < 4; ni++)
#pragma unroll
            for (int e = 0; e < 4; e++) acc[mi][ni][e] = 0.f;

    ldChunk(0, 0); CP_COMMIT;
    CP_WAIT0;
    __syncthreads();

    int p = 0;
    for (int cc = 0; cc < 10; cc++) {
        if (cc < 9) { ldChunk(cc + 1, p ^ 1); CP_COMMIT; }

        const float* Ls = Lsb[p];
        const float* Ws = Wsb[p];
#pragma unroll
        for (int kk = 0; kk < 8; kk++) {
            const int kc = kk * 8;
            uint32_t af[4][4], bf[4][2];
#pragma unroll
            for (int mi = 0; mi < 4; mi++) {
                int r = wm * 64 + mi * 16 + grp;
                af[mi][0] = f2tf(Ls[r * LDL2 + kc + tig]);
                af[mi][1] = f2tf(Ls[(r + 8) * LDL2 + kc + tig]);
                af[mi][2] = f2tf(Ls[r * LDL2 + kc + tig + 4]);
                af[mi][3] = f2tf(Ls[(r + 8) * LDL2 + kc + tig + 4]);
            }
#pragma unroll
            for (int ni = 0; ni < 4; ni++) {
                int cn = wn * 32 + ni * 8 + grp;
                bf[ni][0] = f2tf(Ws[(kc + tig) * LDW2 + cn]);
                bf[ni][1] = f2tf(Ws[(kc + tig + 4) * LDW2 + cn]);
            }
#pragma unroll
            for (int mi = 0; mi < 4; mi++)
#pragma unroll
                for (int ni = 0; ni < 4; ni++)
                    mma8(acc[mi][ni], af[mi], bf[ni]);
        }
        CP_WAIT0;
        __syncthreads();
        p ^= 1;
    }

    // epilogue: tanh + store
#pragma unroll
    for (int mi = 0; mi < 4; mi++) {
        int r0 = wm * 64 + mi * 16 + grp;
        int r1 = r0 + 8;
        float* o0 = &out[((size_t)(s * 1024) + i0 + r0) * 128];
        float* o1 = &out[((size_t)(s * 1024) + i0 + r1) * 128];
#pragma unroll
        for (int ni = 0; ni < 4; ni++) {
            int cn = wn * 32 + ni * 8 + tig * 2;
            *reinterpret_cast<float2*>(o0 + cn) =
                make_float2(fasttanh(acc[mi][ni][0]), fasttanh(acc[mi][ni][1]));
            *reinterpret_cast<float2*>(o1 + cn) =
                make_float2(fasttanh(acc[mi][ni][2]), fasttanh(acc[mi][ni][3]));
        }
    }
}

// ---------------------------------------------------------------------------
extern "C" void kernel_launch(void* const* d_in, const int* in_sizes, int n_in,
                              void* d_out, int out_size)
{
    const float* A     = (const float*)d_in[0];
    const float* x     = (const float*)d_in[1];
    const float* w     = (const float*)d_in[2];
    const float* theta = (const float*)d_in[3];
    float* out = (float*)d_out;

    cudaFuncSetAttribute(k1_gemm, cudaFuncAttributeMaxDynamicSharedMemorySize, SMEM1);
    cudaFuncSetAttribute(k2_agg,  cudaFuncAttributeMaxDynamicSharedMemorySize, SMEM2);

    k0_wt<<<320, 256>>>(w, theta);
    k1_gemm<<<dim3(32, 16), 256, SMEM1>>>(A, x);
    k2_agg<<<dim3(8, 16), 256, SMEM2>>>(x, out);
}

// round 4
// speedup vs baseline: 1.8416x; 1.4816x over previous
#include <cuda_runtime.h>
#include <cuda_fp16.h>
#include <cstdint>

#define EPSV 1e-7f

// Scratch (no cudaMalloc allowed)
__device__ __align__(16) __half g_Mh[16 * 4 * 1024 * 128];  // normalized m, fp16
__device__ __align__(16) __half g_W2h[128 * 640];           // [b][c*128+a], c=4 -> theta
__device__ __align__(16) __half g_xh[16 * 128 * 1024];      // [s][a][j]  (B for k1)
__device__ __align__(16) __half g_xh2[16 * 1024 * 128];     // [s][j][a]  (L chunk for k2)

// ---------------------------------------------------------------------------
__device__ __forceinline__ uint32_t cvta_s(const void* p) {
    uint32_t a;
    asm("{ .reg .u64 t; cvta.to.shared.u64 t, %1; cvt.u32.u64 %0, t; }"
        : "=r"(a) : "l"(p));
    return a;
}
__device__ __forceinline__ uint32_t swz(uint32_t off) {   // SW128-style xor swizzle
    return off ^ ((off >> 3) & 0x70);
}
__device__ __forceinline__ void cpa16(uint32_t d, const void* g) {
    asm volatile("cp.async.cg.shared.global [%0], [%1], 16;" :: "r"(d), "l"(g));
}
#define CPA_COMMIT asm volatile("cp.async.commit_group;")
#define CPA_WAIT0  asm volatile("cp.async.wait_group 0;")

#define LDSM4(r, addr) \
    asm volatile("ldmatrix.sync.aligned.m8n8.x4.shared.b16 {%0,%1,%2,%3}, [%4];" \
        : "=r"((r)[0]), "=r"((r)[1]), "=r"((r)[2]), "=r"((r)[3]) : "r"(addr))

__device__ __forceinline__ void mma16(float* d, const uint32_t* a, const uint32_t* b) {
    asm volatile(
        "mma.sync.aligned.m16n8k16.row.col.f32.f16.f16.f32 "
        "{%0,%1,%2,%3}, {%4,%5,%6,%7}, {%8,%9}, {%0,%1,%2,%3};"
        : "+f"(d[0]), "+f"(d[1]), "+f"(d[2]), "+f"(d[3])
        : "r"(a[0]), "r"(a[1]), "r"(a[2]), "r"(a[3]), "r"(b[0]), "r"(b[1]));
}
__device__ __forceinline__ float fasttanh(float x) {
    float y; asm("tanh.approx.f32 %0, %1;" : "=f"(y) : "f"(x)); return y;
}

// ---------------------------------------------------------------------------
// k0_w: weight[a][b][c] + theta[a][b] -> g_W2h[b][c*128 + a]  (fp16)
// ---------------------------------------------------------------------------
__global__ void k0_w(const float* __restrict__ w, const float* __restrict__ th) {
    int o = blockIdx.x * 256 + threadIdx.x;   // 16384
    int a = o >> 7, b = o & 127;
    float4 v = *reinterpret_cast<const float4*>(w + (size_t)(a * 128 + b) * 4);
    g_W2h[b * 640 + 0 * 128 + a] = __float2half_rn(v.x);
    g_W2h[b * 640 + 1 * 128 + a] = __float2half_rn(v.y);
    g_W2h[b * 640 + 2 * 128 + a] = __float2half_rn(v.z);
    g_W2h[b * 640 + 3 * 128 + a] = __float2half_rn(v.w);
    g_W2h[b * 640 + 4 * 128 + a] = __float2half_rn(th[a * 128 + b]);
}

// ---------------------------------------------------------------------------
// k0_x: x[s][j][a] fp32 -> g_xh[s][a][j] fp16 (transposed) + g_xh2[s][j][a] fp16
// ---------------------------------------------------------------------------
__global__ void k0_x(const float* __restrict__ x) {
    __shared__ float t[32][132];
    const int tid = threadIdx.x;
    const int j0 = blockIdx.x * 32, s = blockIdx.y;
#pragma unroll
    for (int it = 0; it < 4; it++) {
        int f = tid + it * 256;               // < 1024
        int jj = f >> 5, a4 = (f & 31) * 4;
        float4 v = *reinterpret_cast<const float4*>(
            x + ((size_t)(s * 1024 + j0 + jj)) * 128 + a4);
        t[jj][a4] = v.x; t[jj][a4 + 1] = v.y; t[jj][a4 + 2] = v.z; t[jj][a4 + 3] = v.w;
        __half2 h01 = __floats2half2_rn(v.x, v.y);
        __half2 h23 = __floats2half2_rn(v.z, v.w);
        __half2* d = reinterpret_cast<__half2*>(
            g_xh2 + ((size_t)(s * 1024 + j0 + jj)) * 128 + a4);
        d[0] = h01; d[1] = h23;
    }
    __syncthreads();
#pragma unroll
    for (int it = 0; it < 4; it++) {
        int f = tid + it * 256;
        int a = f >> 3, jb = f & 7;
        __half2 h01 = __floats2half2_rn(t[jb * 4 + 0][a], t[jb * 4 + 1][a]);
        __half2 h23 = __floats2half2_rn(t[jb * 4 + 2][a], t[jb * 4 + 3][a]);
        __half2* d = reinterpret_cast<__half2*>(
            g_xh + ((size_t)(s * 128 + a)) * 1024 + j0 + jb * 4);
        d[0] = h01; d[1] = h23;
    }
}

// ---------------------------------------------------------------------------
// Shared tile-MMA block: 16 warps (4M x 4N), M=128, N=128, K-tile=64, fp16.
// acc[2][4][4] per warp. Asm tile [128 rows][64 k] fp16 swizzled, Bsm same.
// ---------------------------------------------------------------------------
#define K1_STAGE 32768
#define SM_AS(st) (512u + (st) * K1_STAGE)
#define SM_BS(st) (512u + (st) * K1_STAGE + 16384u)
#define SMEM_TOT (512 + 2 * K1_STAGE)

__device__ __forceinline__ void mma_tile(float acc[2][4][4], uint32_t As, uint32_t Bs,
                                         int wm, int wn, int lane) {
#pragma unroll
    for (int k16 = 0; k16 < 4; k16++) {
        uint32_t aF[2][4], bF[2][4];
#pragma unroll
        for (int mi = 0; mi < 2; mi++)
            LDSM4(aF[mi], As + swz((uint32_t)((wm * 32 + mi * 16 + (lane & 15)) * 128
                                              + k16 * 32 + (lane >> 4) * 16)));
#pragma unroll
        for (int nb = 0; nb < 2; nb++)
            LDSM4(bF[nb], Bs + swz((uint32_t)((wn * 32 + nb * 16 + ((lane >> 4) << 3)
                                               + (lane & 7)) * 128
                                              + k16 * 32 + ((lane >> 3) & 1) * 16)));
#pragma unroll
        for (int mi = 0; mi < 2; mi++)
#pragma unroll
            for (int nb = 0; nb < 2; nb++) {
                mma16(acc[mi][nb * 2 + 0], aF[mi], &bF[nb][0]);
                mma16(acc[mi][nb * 2 + 1], aF[mi], &bF[nb][2]);
            }
    }
}

// ---------------------------------------------------------------------------
// k1: per (s, 32 i-rows): D[(c,il)][a] = sum_j Ar_c[il][j] * x[j][a]
//     M=128 rows = c*32+il, N=128 = a, K=1024 in 16 tiles of 64.
//     Fused rowsum -> norm in epilogue -> g_Mh (fp16).
// ---------------------------------------------------------------------------
__global__ void __launch_bounds__(512, 1)
k1_gemm(const float* __restrict__ A)
{
    extern __shared__ char sm[];
    const uint32_t sb = cvta_s(sm);
    float* nrm = reinterpret_cast<float*>(sm);

    const int tid = threadIdx.x, warp = tid >> 5, lane = tid & 31;
    const int wm = warp & 3, wn = warp >> 2;
    const int s = blockIdx.y, i0 = blockIdx.x * 32;

    const int il = tid >> 4, hx = tid & 15;       // A-load: row il, 4 j starting j0
    const int j0 = hx * 4;
    const float* Ab = A + ((size_t)(s * 1024 + i0 + il)) * 5120 + hx * 20;
    const __half* xT = g_xh + (size_t)s * 131072;

    float4 areg[5];
    auto ldA = [&](int kt) {
        const float* At = Ab + kt * 320;
#pragma unroll
        for (int q = 0; q < 5; q++)
            areg[q] = *reinterpret_cast<const float4*>(At + q * 4);
    };
    float rs[4] = {0.f, 0.f, 0.f, 0.f};
    auto stsA = [&](int st) {
        float va[20];
#pragma unroll
        for (int q = 0; q < 5; q++) {
            va[q * 4 + 0] = areg[q].x; va[q * 4 + 1] = areg[q].y;
            va[q * 4 + 2] = areg[q].z; va[q * 4 + 3] = areg[q].w;
        }
        const uint32_t base = sb + SM_AS(st);
#pragma unroll
        for (int c = 0; c < 4; c++) {
            float v0 = va[0 * 5 + c], v1 = va[1 * 5 + c];
            float v2 = va[2 * 5 + c], v3 = va[3 * 5 + c];
            rs[c] += (v0 + v1) + (v2 + v3);
            uint32_t ro = (uint32_t)((c * 32 + il) * 128);
            asm volatile("st.shared.b32 [%0], %1;" ::
                "r"(base + swz(ro + (j0 + 0) * 2)),
                "r"(*(uint32_t*)&__floats2half2_rn(v0, v1)) : "memory");
            asm volatile("st.shared.b32 [%0], %1;" ::
                "r"(base + swz(ro + (j0 + 2) * 2)),
                "r"(*(uint32_t*)&__floats2half2_rn(v2, v3)) : "memory");
        }
    };
    auto ldB = [&](int kt, int st) {
        const uint32_t dst = sb + SM_BS(st);
#pragma unroll
        for (int it = 0; it < 2; it++) {
            int f = tid + it * 512;               // < 1024
            int row = f >> 3, ch = f & 7;
            cpa16(dst + swz((uint32_t)(row * 128 + ch * 16)),
                  xT + (size_t)row * 1024 + kt * 64 + ch * 8);
        }
    };

    float acc[2][4][4];
#pragma unroll
    for (int mi = 0; mi < 2; mi++)
#pragma unroll
        for (int ni = 0; ni < 4; ni++)
#pragma unroll
            for (int e = 0; e < 4; e++) acc[mi][ni][e] = 0.f;

    // prologue
    ldB(0, 0); CPA_COMMIT;
    ldA(0); stsA(0);
    ldA(1);
    CPA_WAIT0;
    __syncthreads();

#pragma unroll 1
    for (int kt = 0; kt < 16; kt++) {
        const int p = kt & 1;
        if (kt < 15) { ldB(kt + 1, p ^ 1); CPA_COMMIT; }
        mma_tile(acc, sb + SM_AS(p), sb + SM_BS(p), wm, wn, lane);
        if (kt < 15) {
            stsA(p ^ 1);                          // A(kt+1) from regs
            if (kt < 14) ldA(kt + 2);
            CPA_WAIT0;
            __syncthreads();
        }
    }

    // norm = 1/(rowsum + eps): reduce the 16 threads sharing a row
#pragma unroll
    for (int m = 1; m < 16; m <<= 1)
#pragma unroll
        for (int c = 0; c < 4; c++)
            rs[c] += __shfl_xor_sync(0xffffffff, rs[c], m);
    if (hx == 0)
#pragma unroll
        for (int c = 0; c < 4; c++)
            nrm[c * 32 + il] = 1.0f / (rs[c] + EPSV);
    __syncthreads();

    // epilogue: scale by norm, convert fp16, store g_Mh
#pragma unroll
    for (int mi = 0; mi < 2; mi++) {
        int r0 = wm * 32 + mi * 16 + (lane >> 2);
        int r1 = r0 + 8;
        float nm0 = nrm[r0], nm1 = nrm[r1];
        int c0 = r0 >> 5, il0 = r0 & 31;
        int c1 = r1 >> 5, il1 = r1 & 31;
        __half* d0 = g_Mh + (((size_t)(s * 4 + c0)) * 1024 + i0 + il0) * 128;
        __half* d1 = g_Mh + (((size_t)(s * 4 + c1)) * 1024 + i0 + il1) * 128;
#pragma unroll
        for (int n8 = 0; n8 < 4; n8++) {
            int cn = wn * 32 + n8 * 8 + (lane & 3) * 2;
            *reinterpret_cast<__half2*>(d0 + cn) =
                __floats2half2_rn(acc[mi][n8][0] * nm0, acc[mi][n8][1] * nm0);
            *reinterpret_cast<__half2*>(d1 + cn) =
                __floats2half2_rn(acc[mi][n8][2] * nm1, acc[mi][n8][3] * nm1);
        }
    }
}

// ---------------------------------------------------------------------------
// k2: out = tanh([Mn_0..Mn_3, x] @ W2^T). M=128 i, N=128 b, K=640 (10 tiles).
// ---------------------------------------------------------------------------
__global__ void __launch_bounds__(512, 1)
k2_agg(float* __restrict__ out)
{
    extern __shared__ char sm[];
    const uint32_t sb = cvta_s(sm);
    const int tid = threadIdx.x, warp = tid >> 5, lane = tid & 31;
    const int wm = warp & 3, wn = warp >> 2;
    const int s = blockIdx.y, i0 = blockIdx.x * 128;

    auto ldTile = [&](int kt, int st) {
        const int c = kt >> 1, a0 = (kt & 1) * 64;
        const uint32_t ld = sb + SM_AS(st), wd = sb + SM_BS(st);
#pragma unroll
        for (int it = 0; it < 2; it++) {
            int f = tid + it * 512;               // < 1024
            int row = f >> 3, ch = f & 7;
            const __half* src = (c < 4)
                ? (g_Mh + (((size_t)(s * 4 + c)) * 1024 + i0 + row) * 128 + a0 + ch * 8)
                : (g_xh2 + ((size_t)(s * 1024 + i0 + row)) * 128 + a0 + ch * 8);
            cpa16(ld + swz((uint32_t)(row * 128 + ch * 16)), src);
        }
#pragma unroll
        for (int it = 0; it < 2; it++) {
            int f = tid + it * 512;
            int row = f >> 3, ch = f & 7;
            cpa16(wd + swz((uint32_t)(row * 128 + ch * 16)),
                  g_W2h + (size_t)row * 640 + kt * 64 + ch * 8);
        }
    };

    float acc[2][4][4];
#pragma unroll
    for (int mi = 0; mi < 2; mi++)
#pragma unroll
        for (int ni = 0; ni < 4; ni++)
#pragma unroll
            for (int e = 0; e < 4; e++) acc[mi][ni][e] = 0.f;

    ldTile(0, 0); CPA_COMMIT;
    CPA_WAIT0;
    __syncthreads();

#pragma unroll 1
    for (int kt = 0; kt < 10; kt++) {
        const int p = kt & 1;
        if (kt < 9) { ldTile(kt + 1, p ^ 1); CPA_COMMIT; }
        mma_tile(acc, sb + SM_AS(p), sb + SM_BS(p), wm, wn, lane);
        if (kt < 9) { CPA_WAIT0; __syncthreads(); }
    }

    // epilogue: tanh + fp32 store
#pragma unroll
    for (int mi = 0; mi < 2; mi++) {
        int r0 = i0 + wm * 32 + mi * 16 + (lane >> 2);
        float* o0 = out + ((size_t)(s * 1024) + r0) * 128;
        float* o1 = out + ((size_t)(s * 1024) + r0 + 8) * 128;
#pragma unroll
        for (int n8 = 0; n8 < 4; n8++) {
            int cn = wn * 32 + n8 * 8 + (lane & 3) * 2;
            *reinterpret_cast<float2*>(o0 + cn) =
                make_float2(fasttanh(acc[mi][n8][0]), fasttanh(acc[mi][n8][1]));
            *reinterpret_cast<float2*>(o1 + cn) =
                make_float2(fasttanh(acc[mi][n8][2]), fasttanh(acc[mi][n8][3]));
        }
    }
}

// ---------------------------------------------------------------------------
extern "C" void kernel_launch(void* const* d_in, const int* in_sizes, int n_in,
                              void* d_out, int out_size)
{
    const float* A     = (const float*)d_in[0];
    const float* x     = (const float*)d_in[1];
    const float* w     = (const float*)d_in[2];
    const float* theta = (const float*)d_in[3];
    float* out = (float*)d_out;

    cudaFuncSetAttribute(k1_gemm, cudaFuncAttributeMaxDynamicSharedMemorySize, SMEM_TOT);
    cudaFuncSetAttribute(k2_agg,  cudaFuncAttributeMaxDynamicSharedMemorySize, SMEM_TOT);

    k0_w<<<64, 256>>>(w, theta);
    k0_x<<<dim3(32, 16), 256>>>(x);
    k1_gemm<<<dim3(32, 16), 512, SMEM_TOT>>>(A);
    k2_agg<<<dim3(8, 16), 512, SMEM_TOT>>>(out);
}

// round 5
// speedup vs baseline: 2.7324x; 1.4837x over previous
#include <cuda_runtime.h>
#include <cuda_fp16.h>
#include <cstdint>

#define EPSV 1e-7f

// Scratch (no cudaMalloc allowed)
__device__ __align__(16) __half g_Mh[16 * 4 * 1024 * 128];  // normalized m, fp16
__device__ __align__(16) __half g_W2h[128 * 640];           // [b][c*128+a], c=4 -> theta
__device__ __align__(16) __half g_xh[16 * 128 * 1024];      // [s][a][j]  (B for k1)
__device__ __align__(16) __half g_xh2[16 * 1024 * 128];     // [s][j][a]  (L chunk for k2)

// ---------------------------------------------------------------------------
__device__ __forceinline__ uint32_t cvta_s(const void* p) {
    uint32_t a;
    asm("{ .reg .u64 t; cvta.to.shared.u64 t, %1; cvt.u32.u64 %0, t; }"
        : "=r"(a) : "l"(p));
    return a;
}
__device__ __forceinline__ uint32_t swz(uint32_t off) {   // SW128-style xor swizzle
    return off ^ ((off >> 3) & 0x70);
}
__device__ __forceinline__ void cpa16(uint32_t d, const void* g) {
    asm volatile("cp.async.cg.shared.global [%0], [%1], 16;" :: "r"(d), "l"(g));
}
#define CPA_COMMIT asm volatile("cp.async.commit_group;")
#define CPA_WAIT0  asm volatile("cp.async.wait_group 0;")

#define LDSM4(r, addr) \
    asm volatile("ldmatrix.sync.aligned.m8n8.x4.shared.b16 {%0,%1,%2,%3}, [%4];" \
        : "=r"((r)[0]), "=r"((r)[1]), "=r"((r)[2]), "=r"((r)[3]) : "r"(addr))

__device__ __forceinline__ void mma16(float* d, const uint32_t* a, const uint32_t* b) {
    asm volatile(
        "mma.sync.aligned.m16n8k16.row.col.f32.f16.f16.f32 "
        "{%0,%1,%2,%3}, {%4,%5,%6,%7}, {%8,%9}, {%0,%1,%2,%3};"
        : "+f"(d[0]), "+f"(d[1]), "+f"(d[2]), "+f"(d[3])
        : "r"(a[0]), "r"(a[1]), "r"(a[2]), "r"(a[3]), "r"(b[0]), "r"(b[1]));
}
__device__ __forceinline__ float fasttanh(float x) {
    float y; asm("tanh.approx.f32 %0, %1;" : "=f"(y) : "f"(x)); return y;
}

// ---------------------------------------------------------------------------
// k0_w: weight[a][b][c] + theta[a][b] -> g_W2h[b][c*128 + a]  (fp16)
// ---------------------------------------------------------------------------
__global__ void k0_w(const float* __restrict__ w, const float* __restrict__ th) {
    int o = blockIdx.x * 256 + threadIdx.x;   // 16384
    int a = o >> 7, b = o & 127;
    float4 v = *reinterpret_cast<const float4*>(w + (size_t)(a * 128 + b) * 4);
    g_W2h[b * 640 + 0 * 128 + a] = __float2half_rn(v.x);
    g_W2h[b * 640 + 1 * 128 + a] = __float2half_rn(v.y);
    g_W2h[b * 640 + 2 * 128 + a] = __float2half_rn(v.z);
    g_W2h[b * 640 + 3 * 128 + a] = __float2half_rn(v.w);
    g_W2h[b * 640 + 4 * 128 + a] = __float2half_rn(th[a * 128 + b]);
}

// ---------------------------------------------------------------------------
// k0_x: x[s][j][a] fp32 -> g_xh[s][a][j] fp16 (transposed) + g_xh2[s][j][a] fp16
// ---------------------------------------------------------------------------
__global__ void k0_x(const float* __restrict__ x) {
    __shared__ float t[32][132];
    const int tid = threadIdx.x;
    const int j0 = blockIdx.x * 32, s = blockIdx.y;
#pragma unroll
    for (int it = 0; it < 4; it++) {
        int f = tid + it * 256;               // < 1024
        int jj = f >> 5, a4 = (f & 31) * 4;
        float4 v = *reinterpret_cast<const float4*>(
            x + ((size_t)(s * 1024 + j0 + jj)) * 128 + a4);
        t[jj][a4] = v.x; t[jj][a4 + 1] = v.y; t[jj][a4 + 2] = v.z; t[jj][a4 + 3] = v.w;
        __half2 h01 = __floats2half2_rn(v.x, v.y);
        __half2 h23 = __floats2half2_rn(v.z, v.w);
        __half2* d = reinterpret_cast<__half2*>(
            g_xh2 + ((size_t)(s * 1024 + j0 + jj)) * 128 + a4);
        d[0] = h01; d[1] = h23;
    }
    __syncthreads();
#pragma unroll
    for (int it = 0; it < 4; it++) {
        int f = tid + it * 256;
        int a = f >> 3, jb = f & 7;
        __half2 h01 = __floats2half2_rn(t[jb * 4 + 0][a], t[jb * 4 + 1][a]);
        __half2 h23 = __floats2half2_rn(t[jb * 4 + 2][a], t[jb * 4 + 3][a]);
        __half2* d = reinterpret_cast<__half2*>(
            g_xh + ((size_t)(s * 128 + a)) * 1024 + j0 + jb * 4);
        d[0] = h01; d[1] = h23;
    }
}

// ---------------------------------------------------------------------------
// Shared tile-MMA: 8 warps (2M x 4N), M=64, N=128, K-tile=64 fp16.
// A tile: [64 rows][64 k] swizzled (8KB). B tile: [128 n][64 k] (16KB).
// ---------------------------------------------------------------------------
#define STAGE_B   24576
#define SM_AS(st) (512u + (st) * STAGE_B)
#define SM_BS(st) (512u + (st) * STAGE_B + 8192u)
#define SMEM_TOT  (512 + 2 * STAGE_B)

__device__ __forceinline__ void mma_tile(float acc[2][4][4], uint32_t As, uint32_t Bs,
                                         int wm, int wn, int lane) {
#pragma unroll
    for (int k16 = 0; k16 < 4; k16++) {
        uint32_t aF[2][4], bF[2][4];
#pragma unroll
        for (int mi = 0; mi < 2; mi++)
            LDSM4(aF[mi], As + swz((uint32_t)((wm * 32 + mi * 16 + (lane & 15)) * 128
                                              + k16 * 32 + (lane >> 4) * 16)));
#pragma unroll
        for (int nb = 0; nb < 2; nb++)
            LDSM4(bF[nb], Bs + swz((uint32_t)((wn * 32 + nb * 16 + ((lane >> 4) << 3)
                                               + (lane & 7)) * 128
                                              + k16 * 32 + ((lane >> 3) & 1) * 16)));
#pragma unroll
        for (int mi = 0; mi < 2; mi++)
#pragma unroll
            for (int nb = 0; nb < 2; nb++) {
                mma16(acc[mi][nb * 2 + 0], aF[mi], &bF[nb][0]);
                mma16(acc[mi][nb * 2 + 1], aF[mi], &bF[nb][2]);
            }
    }
}

// ---------------------------------------------------------------------------
// k1: per (s, 16 i-rows): D[(c,il)][a] = sum_j Ar_c[il][j] * x[j][a]
//     M=64 rows = c*16+il, N=128 = a, K=1024 in 16 tiles of 64.
//     Fused rowsum -> norm in epilogue -> g_Mh (fp16). 1024 CTAs, 2/SM.
// ---------------------------------------------------------------------------
__global__ void __launch_bounds__(256, 2)
k1_gemm(const float* __restrict__ A)
{
    extern __shared__ char sm[];
    const uint32_t sb = cvta_s(sm);
    float* nrm = reinterpret_cast<float*>(sm);   // [64]

    const int tid = threadIdx.x, warp = tid >> 5, lane = tid & 31;
    const int wm = warp & 1, wn = warp >> 1;
    const int s = blockIdx.y, i0 = blockIdx.x * 16;

    const int il = tid >> 4, hx = tid & 15;       // A-load: row il (0..15), 4 j's
    const int j0 = hx * 4;
    const float* Ab = A + ((size_t)(s * 1024 + i0 + il)) * 5120 + hx * 20;
    const __half* xT = g_xh + (size_t)s * 131072;

    float4 areg[5];
    auto ldA = [&](int kt) {
        const float* At = Ab + kt * 320;
#pragma unroll
        for (int q = 0; q < 5; q++)
            areg[q] = *reinterpret_cast<const float4*>(At + q * 4);
    };
    float rs[4] = {0.f, 0.f, 0.f, 0.f};
    auto stsA = [&](int st) {
        float va[20];
#pragma unroll
        for (int q = 0; q < 5; q++) {
            va[q * 4 + 0] = areg[q].x; va[q * 4 + 1] = areg[q].y;
            va[q * 4 + 2] = areg[q].z; va[q * 4 + 3] = areg[q].w;
        }
        const uint32_t base = sb + SM_AS(st);
#pragma unroll
        for (int c = 0; c < 4; c++) {
            float v0 = va[0 * 5 + c], v1 = va[1 * 5 + c];
            float v2 = va[2 * 5 + c], v3 = va[3 * 5 + c];
            rs[c] += (v0 + v1) + (v2 + v3);
            uint32_t ro = (uint32_t)((c * 16 + il) * 128);
            asm volatile("st.shared.b32 [%0], %1;" ::
                "r"(base + swz(ro + (j0 + 0) * 2)),
                "r"(*(uint32_t*)&__floats2half2_rn(v0, v1)) : "memory");
            asm volatile("st.shared.b32 [%0], %1;" ::
                "r"(base + swz(ro + (j0 + 2) * 2)),
                "r"(*(uint32_t*)&__floats2half2_rn(v2, v3)) : "memory");
        }
    };
    auto ldB = [&](int kt, int st) {
        const uint32_t dst = sb + SM_BS(st);
#pragma unroll
        for (int it = 0; it < 4; it++) {
            int f = tid + it * 256;               // < 1024 (128 rows x 8 chunks)
            int row = f >> 3, ch = f & 7;
            cpa16(dst + swz((uint32_t)(row * 128 + ch * 16)),
                  xT + (size_t)row * 1024 + kt * 64 + ch * 8);
        }
    };

    float acc[2][4][4];
#pragma unroll
    for (int mi = 0; mi < 2; mi++)
#pragma unroll
        for (int ni = 0; ni < 4; ni++)
#pragma unroll
            for (int e = 0; e < 4; e++) acc[mi][ni][e] = 0.f;

    // prologue
    ldB(0, 0); CPA_COMMIT;
    ldA(0); stsA(0);
    ldA(1);
    CPA_WAIT0;
    __syncthreads();

#pragma unroll 1
    for (int kt = 0; kt < 16; kt++) {
        const int p = kt & 1;
        if (kt < 15) { ldB(kt + 1, p ^ 1); CPA_COMMIT; }
        mma_tile(acc, sb + SM_AS(p), sb + SM_BS(p), wm, wn, lane);
        if (kt < 15) {
            stsA(p ^ 1);                          // A(kt+1) from regs
            if (kt < 14) ldA(kt + 2);
            CPA_WAIT0;
            __syncthreads();
        }
    }

    // norm = 1/(rowsum + eps): reduce 16 threads sharing a row
#pragma unroll
    for (int m = 1; m < 16; m <<= 1)
#pragma unroll
        for (int c = 0; c < 4; c++)
            rs[c] += __shfl_xor_sync(0xffffffff, rs[c], m);
    if (hx == 0)
#pragma unroll
        for (int c = 0; c < 4; c++)
            nrm[c * 16 + il] = 1.0f / (rs[c] + EPSV);
    __syncthreads();

    // epilogue: scale by norm, convert fp16, store g_Mh
#pragma unroll
    for (int mi = 0; mi < 2; mi++) {
        int r0 = wm * 32 + mi * 16 + (lane >> 2);
        int r1 = r0 + 8;
        float nm0 = nrm[r0], nm1 = nrm[r1];
        int c0 = r0 >> 4, il0 = r0 & 15;
        int c1 = r1 >> 4, il1 = r1 & 15;
        __half* d0 = g_Mh + (((size_t)(s * 4 + c0)) * 1024 + i0 + il0) * 128;
        __half* d1 = g_Mh + (((size_t)(s * 4 + c1)) * 1024 + i0 + il1) * 128;
#pragma unroll
        for (int n8 = 0; n8 < 4; n8++) {
            int cn = wn * 32 + n8 * 8 + (lane & 3) * 2;
            *reinterpret_cast<__half2*>(d0 + cn) =
                __floats2half2_rn(acc[mi][n8][0] * nm0, acc[mi][n8][1] * nm0);
            *reinterpret_cast<__half2*>(d1 + cn) =
                __floats2half2_rn(acc[mi][n8][2] * nm1, acc[mi][n8][3] * nm1);
        }
    }
}

// ---------------------------------------------------------------------------
// k2: out = tanh([Mn_0..Mn_3, x] @ W2^T). M=64 i, N=128 b, K=640 (10 tiles).
// 256 CTAs, 2/SM.
// ---------------------------------------------------------------------------
__global__ void __launch_bounds__(256, 2)
k2_agg(float* __restrict__ out)
{
    extern __shared__ char sm[];
    const uint32_t sb = cvta_s(sm);
    const int tid = threadIdx.x, warp = tid >> 5, lane = tid & 31;
    const int wm = warp & 1, wn = warp >> 1;
    const int s = blockIdx.y, i0 = blockIdx.x * 64;

    auto ldTile = [&](int kt, int st) {
        const int c = kt >> 1, a0 = (kt & 1) * 64;
        const uint32_t ld = sb + SM_AS(st), wd = sb + SM_BS(st);
        {
            int f = tid;                          // 512: 64 rows x 8 chunks
            int row = f >> 3, ch = f & 7;
            const __half* src = (c < 4)
                ? (g_Mh + (((size_t)(s * 4 + c)) * 1024 + i0 + row) * 128 + a0 + ch * 8)
                : (g_xh2 + ((size_t)(s * 1024 + i0 + row)) * 128 + a0 + ch * 8);
            cpa16(ld + swz((uint32_t)(row * 128 + ch * 16)), src);
            int f2 = tid + 256;
            int row2 = f2 >> 3, ch2 = f2 & 7;
            const __half* src2 = (c < 4)
                ? (g_Mh + (((size_t)(s * 4 + c)) * 1024 + i0 + row2) * 128 + a0 + ch2 * 8)
                : (g_xh2 + ((size_t)(s * 1024 + i0 + row2)) * 128 + a0 + ch2 * 8);
            cpa16(ld + swz((uint32_t)(row2 * 128 + ch2 * 16)), src2);
        }
#pragma unroll
        for (int it = 0; it < 4; it++) {          // W: 128 rows x 8 chunks
            int f = tid + it * 256;
            int row = f >> 3, ch = f & 7;
            cpa16(wd + swz((uint32_t)(row * 128 + ch * 16)),
                  g_W2h + (size_t)row * 640 + kt * 64 + ch * 8);
        }
    };

    float acc[2][4][4];
#pragma unroll
    for (int mi = 0; mi < 2; mi++)
#pragma unroll
        for (int ni = 0; ni < 4; ni++)
#pragma unroll
            for (int e = 0; e < 4; e++) acc[mi][ni][e] = 0.f;

    ldTile(0, 0); CPA_COMMIT;
    CPA_WAIT0;
    __syncthreads();

#pragma unroll 1
    for (int kt = 0; kt < 10; kt++) {
        const int p = kt & 1;
        if (kt < 9) { ldTile(kt + 1, p ^ 1); CPA_COMMIT; }
        mma_tile(acc, sb + SM_AS(p), sb + SM_BS(p), wm, wn, lane);
        if (kt < 9) { CPA_WAIT0; __syncthreads(); }
    }

    // epilogue: tanh + fp32 store
#pragma unroll
    for (int mi = 0; mi < 2; mi++) {
        int r0 = i0 + wm * 32 + mi * 16 + (lane >> 2);
        float* o0 = out + ((size_t)(s * 1024) + r0) * 128;
        float* o1 = out + ((size_t)(s * 1024) + r0 + 8) * 128;
#pragma unroll
        for (int n8 = 0; n8 < 4; n8++) {
            int cn = wn * 32 + n8 * 8 + (lane & 3) * 2;
            *reinterpret_cast<float2*>(o0 + cn) =
                make_float2(fasttanh(acc[mi][n8][0]), fasttanh(acc[mi][n8][1]));
            *reinterpret_cast<float2*>(o1 + cn) =
                make_float2(fasttanh(acc[mi][n8][2]), fasttanh(acc[mi][n8][3]));
        }
    }
}

// ---------------------------------------------------------------------------
extern "C" void kernel_launch(void* const* d_in, const int* in_sizes, int n_in,
                              void* d_out, int out_size)
{
    const float* A     = (const float*)d_in[0];
    const float* x     = (const float*)d_in[1];
    const float* w     = (const float*)d_in[2];
    const float* theta = (const float*)d_in[3];
    float* out = (float*)d_out;

    cudaFuncSetAttribute(k1_gemm, cudaFuncAttributeMaxDynamicSharedMemorySize, SMEM_TOT);
    cudaFuncSetAttribute(k2_agg,  cudaFuncAttributeMaxDynamicSharedMemorySize, SMEM_TOT);

    k0_w<<<64, 256>>>(w, theta);
    k0_x<<<dim3(32, 16), 256>>>(x);
    k1_gemm<<<dim3(64, 16), 256, SMEM_TOT>>>(A);
    k2_agg<<<dim3(16, 16), 256, SMEM_TOT>>>(out);
}

// round 6
// speedup vs baseline: 2.7828x; 1.0184x over previous
#include <cuda_runtime.h>
#include <cuda_fp16.h>
#include <cstdint>

#define EPSV 1e-7f

// Scratch (no cudaMalloc allowed)
__device__ __align__(16) __half g_Mh[16 * 4 * 1024 * 128];  // normalized m, fp16
__device__ __align__(16) __half g_W2h[128 * 640];           // [b][c*128+a], c=4 -> theta
__device__ __align__(16) __half g_xh[16 * 128 * 1024];      // [s][a][j]  (B for k1)
__device__ __align__(16) __half g_xh2[16 * 1024 * 128];     // [s][j][a]  (L chunk for k2)

// ---------------------------------------------------------------------------
__device__ __forceinline__ uint32_t cvta_s(const void* p) {
    uint32_t a;
    asm("{ .reg .u64 t; cvta.to.shared.u64 t, %1; cvt.u32.u64 %0, t; }"
        : "=r"(a) : "l"(p));
    return a;
}
__device__ __forceinline__ uint32_t swz(uint32_t off) {   // SW128-style xor swizzle
    return off ^ ((off >> 3) & 0x70);
}
__device__ __forceinline__ void cpa16(uint32_t d, const void* g) {
    asm volatile("cp.async.cg.shared.global [%0], [%1], 16;" :: "r"(d), "l"(g));
}
#define CPA_COMMIT asm volatile("cp.async.commit_group;")
#define CPA_WAIT0  asm volatile("cp.async.wait_group 0;")
#define CPA_WAIT1  asm volatile("cp.async.wait_group 1;")

#define LDSM4(r, addr) \
    asm volatile("ldmatrix.sync.aligned.m8n8.x4.shared.b16 {%0,%1,%2,%3}, [%4];" \
        : "=r"((r)[0]), "=r"((r)[1]), "=r"((r)[2]), "=r"((r)[3]) : "r"(addr))

__device__ __forceinline__ void mma16(float* d, const uint32_t* a, const uint32_t* b) {
    asm volatile(
        "mma.sync.aligned.m16n8k16.row.col.f32.f16.f16.f32 "
        "{%0,%1,%2,%3}, {%4,%5,%6,%7}, {%8,%9}, {%0,%1,%2,%3};"
        : "+f"(d[0]), "+f"(d[1]), "+f"(d[2]), "+f"(d[3])
        : "r"(a[0]), "r"(a[1]), "r"(a[2]), "r"(a[3]), "r"(b[0]), "r"(b[1]));
}
__device__ __forceinline__ float fasttanh(float x) {
    float y; asm("tanh.approx.f32 %0, %1;" : "=f"(y) : "f"(x)); return y;
}

// ---------------------------------------------------------------------------
// k0_w: weight[a][b][c] + theta[a][b] -> g_W2h[b][c*128 + a]  (fp16)
// ---------------------------------------------------------------------------
__global__ void k0_w(const float* __restrict__ w, const float* __restrict__ th) {
    int o = blockIdx.x * 256 + threadIdx.x;   // 16384
    int a = o >> 7, b = o & 127;
    float4 v = *reinterpret_cast<const float4*>(w + (size_t)(a * 128 + b) * 4);
    g_W2h[b * 640 + 0 * 128 + a] = __float2half_rn(v.x);
    g_W2h[b * 640 + 1 * 128 + a] = __float2half_rn(v.y);
    g_W2h[b * 640 + 2 * 128 + a] = __float2half_rn(v.z);
    g_W2h[b * 640 + 3 * 128 + a] = __float2half_rn(v.w);
    g_W2h[b * 640 + 4 * 128 + a] = __float2half_rn(th[a * 128 + b]);
}

// ---------------------------------------------------------------------------
// k0_x: x[s][j][a] fp32 -> g_xh[s][a][j] fp16 (transposed) + g_xh2[s][j][a] fp16
// ---------------------------------------------------------------------------
__global__ void k0_x(const float* __restrict__ x) {
    __shared__ float t[32][132];
    const int tid = threadIdx.x;
    const int j0 = blockIdx.x * 32, s = blockIdx.y;
#pragma unroll
    for (int it = 0; it < 4; it++) {
        int f = tid + it * 256;               // < 1024
        int jj = f >> 5, a4 = (f & 31) * 4;
        float4 v = *reinterpret_cast<const float4*>(
            x + ((size_t)(s * 1024 + j0 + jj)) * 128 + a4);
        t[jj][a4] = v.x; t[jj][a4 + 1] = v.y; t[jj][a4 + 2] = v.z; t[jj][a4 + 3] = v.w;
        __half2 h01 = __floats2half2_rn(v.x, v.y);
        __half2 h23 = __floats2half2_rn(v.z, v.w);
        __half2* d = reinterpret_cast<__half2*>(
            g_xh2 + ((size_t)(s * 1024 + j0 + jj)) * 128 + a4);
        d[0] = h01; d[1] = h23;
    }
    __syncthreads();
#pragma unroll
    for (int it = 0; it < 4; it++) {
        int f = tid + it * 256;
        int a = f >> 3, jb = f & 7;
        __half2 h01 = __floats2half2_rn(t[jb * 4 + 0][a], t[jb * 4 + 1][a]);
        __half2 h23 = __floats2half2_rn(t[jb * 4 + 2][a], t[jb * 4 + 3][a]);
        __half2* d = reinterpret_cast<__half2*>(
            g_xh + ((size_t)(s * 128 + a)) * 1024 + j0 + jb * 4);
        d[0] = h01; d[1] = h23;
    }
}

// ---------------------------------------------------------------------------
// Shared tile-MMA: 8 warps (2M x 4N), M=64, N=128, K-tile=64 fp16.
// A tile: [64 rows][64 k] swizzled (8KB). B tile: [128 n][64 k] (16KB). 3 stages.
// ---------------------------------------------------------------------------
#define STAGE_B   24576
#define SM_AS(st) (512u + (st) * STAGE_B)
#define SM_BS(st) (512u + (st) * STAGE_B + 8192u)
#define SMEM_TOT  (512 + 3 * STAGE_B)

__device__ __forceinline__ void mma_tile(float acc[2][4][4], uint32_t As, uint32_t Bs,
                                         int wm, int wn, int lane) {
#pragma unroll
    for (int k16 = 0; k16 < 4; k16++) {
        uint32_t aF[2][4], bF[2][4];
#pragma unroll
        for (int mi = 0; mi < 2; mi++)
            LDSM4(aF[mi], As + swz((uint32_t)((wm * 32 + mi * 16 + (lane & 15)) * 128
                                              + k16 * 32 + (lane >> 4) * 16)));
#pragma unroll
        for (int nb = 0; nb < 2; nb++)
            LDSM4(bF[nb], Bs + swz((uint32_t)((wn * 32 + nb * 16 + ((lane >> 4) << 3)
                                               + (lane & 7)) * 128
                                              + k16 * 32 + ((lane >> 3) & 1) * 16)));
#pragma unroll
        for (int mi = 0; mi < 2; mi++)
#pragma unroll
            for (int nb = 0; nb < 2; nb++) {
                mma16(acc[mi][nb * 2 + 0], aF[mi], &bF[nb][0]);
                mma16(acc[mi][nb * 2 + 1], aF[mi], &bF[nb][2]);
            }
    }
}

// ---------------------------------------------------------------------------
// k1: per (s, 16 i-rows): D[(c,il)][a] = sum_j Ar_c[il][j] * x[j][a]
//     M=64 rows = c*16+il, N=128, K=1024 in 16 tiles of 64. 3-stage ring:
//     B cp.async issued 2 tiles ahead (wait_group 1), A reg-staged 2 ahead.
// ---------------------------------------------------------------------------
__global__ void __launch_bounds__(256, 2)
k1_gemm(const float* __restrict__ A)
{
    extern __shared__ char sm[];
    const uint32_t sb = cvta_s(sm);
    float* nrm = reinterpret_cast<float*>(sm);   // [64]

    const int tid = threadIdx.x, warp = tid >> 5, lane = tid & 31;
    const int wm = warp & 1, wn = warp >> 1;
    const int s = blockIdx.y, i0 = blockIdx.x * 16;

    const int il = tid >> 4, hx = tid & 15;       // A-load: row il (0..15), 4 j's
    const int j0 = hx * 4;
    const float* Ab = A + ((size_t)(s * 1024 + i0 + il)) * 5120 + hx * 20;
    const __half* xT = g_xh + (size_t)s * 131072;

    float4 areg[5];
    auto ldA = [&](int kt) {
        const float* At = Ab + kt * 320;
#pragma unroll
        for (int q = 0; q < 5; q++)
            areg[q] = *reinterpret_cast<const float4*>(At + q * 4);
    };
    float rs[4] = {0.f, 0.f, 0.f, 0.f};
    auto stsA = [&](int st) {
        float va[20];
#pragma unroll
        for (int q = 0; q < 5; q++) {
            va[q * 4 + 0] = areg[q].x; va[q * 4 + 1] = areg[q].y;
            va[q * 4 + 2] = areg[q].z; va[q * 4 + 3] = areg[q].w;
        }
        const uint32_t base = sb + SM_AS(st);
#pragma unroll
        for (int c = 0; c < 4; c++) {
            float v0 = va[0 * 5 + c], v1 = va[1 * 5 + c];
            float v2 = va[2 * 5 + c], v3 = va[3 * 5 + c];
            rs[c] += (v0 + v1) + (v2 + v3);
            uint32_t ro = (uint32_t)((c * 16 + il) * 128);
            asm volatile("st.shared.b32 [%0], %1;" ::
                "r"(base + swz(ro + (j0 + 0) * 2)),
                "r"(*(uint32_t*)&__floats2half2_rn(v0, v1)) : "memory");
            asm volatile("st.shared.b32 [%0], %1;" ::
                "r"(base + swz(ro + (j0 + 2) * 2)),
                "r"(*(uint32_t*)&__floats2half2_rn(v2, v3)) : "memory");
        }
    };
    auto ldB = [&](int kt, int st) {
        const uint32_t dst = sb + SM_BS(st);
#pragma unroll
        for (int it = 0; it < 4; it++) {
            int f = tid + it * 256;               // < 1024 (128 rows x 8 chunks)
            int row = f >> 3, ch = f & 7;
            cpa16(dst + swz((uint32_t)(row * 128 + ch * 16)),
                  xT + (size_t)row * 1024 + kt * 64 + ch * 8);
        }
    };

    float acc[2][4][4];
#pragma unroll
    for (int mi = 0; mi < 2; mi++)
#pragma unroll
        for (int ni = 0; ni < 4; ni++)
#pragma unroll
            for (int e = 0; e < 4; e++) acc[mi][ni][e] = 0.f;

    // prologue: B0,B1 in flight; A0,A1 staged; regs hold A2
    ldB(0, 0); CPA_COMMIT;
    ldB(1, 1); CPA_COMMIT;
    ldA(0); stsA(0);
    ldA(1); stsA(1);
    ldA(2);

#pragma unroll 1
    for (int kt = 0; kt < 16; kt++) {
        const int st = kt % 3;
        if (kt < 15) { CPA_WAIT1; } else { CPA_WAIT0; }
        __syncthreads();
        if (kt + 2 < 16) { ldB(kt + 2, (kt + 2) % 3); CPA_COMMIT; }
        mma_tile(acc, sb + SM_AS(st), sb + SM_BS(st), wm, wn, lane);
        if (kt + 2 < 16) {
            stsA((kt + 2) % 3);                   // A(kt+2) from regs
            if (kt + 3 < 16) ldA(kt + 3);
        }
    }

    // norm = 1/(rowsum + eps): reduce 16 threads sharing a row
#pragma unroll
    for (int m = 1; m < 16; m <<= 1)
#pragma unroll
        for (int c = 0; c < 4; c++)
            rs[c] += __shfl_xor_sync(0xffffffff, rs[c], m);
    __syncthreads();
    if (hx == 0)
#pragma unroll
        for (int c = 0; c < 4; c++)
            nrm[c * 16 + il] = 1.0f / (rs[c] + EPSV);
    __syncthreads();

    // epilogue: scale by norm, convert fp16, store g_Mh
#pragma unroll
    for (int mi = 0; mi < 2; mi++) {
        int r0 = wm * 32 + mi * 16 + (lane >> 2);
        int r1 = r0 + 8;
        float nm0 = nrm[r0], nm1 = nrm[r1];
        int c0 = r0 >> 4, il0 = r0 & 15;
        int c1 = r1 >> 4, il1 = r1 & 15;
        __half* d0 = g_Mh + (((size_t)(s * 4 + c0)) * 1024 + i0 + il0) * 128;
        __half* d1 = g_Mh + (((size_t)(s * 4 + c1)) * 1024 + i0 + il1) * 128;
#pragma unroll
        for (int n8 = 0; n8 < 4; n8++) {
            int cn = wn * 32 + n8 * 8 + (lane & 3) * 2;
            *reinterpret_cast<__half2*>(d0 + cn) =
                __floats2half2_rn(acc[mi][n8][0] * nm0, acc[mi][n8][1] * nm0);
            *reinterpret_cast<__half2*>(d1 + cn) =
                __floats2half2_rn(acc[mi][n8][2] * nm1, acc[mi][n8][3] * nm1);
        }
    }
}

// ---------------------------------------------------------------------------
// k2: out = tanh([Mn_0..Mn_3, x] @ W2^T). M=64 i, N=128 b, K=640 (10 tiles).
// 3-stage, loads issued 2 tiles ahead.
// ---------------------------------------------------------------------------
__global__ void __launch_bounds__(256, 2)
k2_agg(float* __restrict__ out)
{
    extern __shared__ char sm[];
    const uint32_t sb = cvta_s(sm);
    const int tid = threadIdx.x, warp = tid >> 5, lane = tid & 31;
    const int wm = warp & 1, wn = warp >> 1;
    const int s = blockIdx.y, i0 = blockIdx.x * 64;

    auto ldTile = [&](int kt, int st) {
        const int c = kt >> 1, a0 = (kt & 1) * 64;
        const uint32_t ld = sb + SM_AS(st), wd = sb + SM_BS(st);
#pragma unroll
        for (int it = 0; it < 2; it++) {          // L: 64 rows x 8 chunks
            int f = tid + it * 256;               // < 512
            int row = f >> 3, ch = f & 7;
            const __half* src = (c < 4)
                ? (g_Mh + (((size_t)(s * 4 + c)) * 1024 + i0 + row) * 128 + a0 + ch * 8)
                : (g_xh2 + ((size_t)(s * 1024 + i0 + row)) * 128 + a0 + ch * 8);
            cpa16(ld + swz((uint32_t)(row * 128 + ch * 16)), src);
        }
#pragma unroll
        for (int it = 0; it < 4; it++) {          // W: 128 rows x 8 chunks
            int f = tid + it * 256;
            int row = f >> 3, ch = f & 7;
            cpa16(wd + swz((uint32_t)(row * 128 + ch * 16)),
                  g_W2h + (size_t)row * 640 + kt * 64 + ch * 8);
        }
    };

    float acc[2][4][4];
#pragma unroll
    for (int mi = 0; mi < 2; mi++)
#pragma unroll
        for (int ni = 0; ni < 4; ni++)
#pragma unroll
            for (int e = 0; e < 4; e++) acc[mi][ni][e] = 0.f;

    ldTile(0, 0); CPA_COMMIT;
    ldTile(1, 1); CPA_COMMIT;

#pragma unroll 1
    for (int kt = 0; kt < 10; kt++) {
        const int st = kt % 3;
        if (kt < 9) { CPA_WAIT1; } else { CPA_WAIT0; }
        __syncthreads();
        if (kt + 2 < 10) { ldTile(kt + 2, (kt + 2) % 3); CPA_COMMIT; }
        mma_tile(acc, sb + SM_AS(st), sb + SM_BS(st), wm, wn, lane);
    }

    // epilogue: tanh + fp32 store
#pragma unroll
    for (int mi = 0; mi < 2; mi++) {
        int r0 = i0 + wm * 32 + mi * 16 + (lane >> 2);
        float* o0 = out + ((size_t)(s * 1024) + r0) * 128;
        float* o1 = out + ((size_t)(s * 1024) + r0 + 8) * 128;
#pragma unroll
        for (int n8 = 0; n8 < 4; n8++) {
            int cn = wn * 32 + n8 * 8 + (lane & 3) * 2;
            *reinterpret_cast<float2*>(o0 + cn) =
                make_float2(fasttanh(acc[mi][n8][0]), fasttanh(acc[mi][n8][1]));
            *reinterpret_cast<float2*>(o1 + cn) =
                make_float2(fasttanh(acc[mi][n8][2]), fasttanh(acc[mi][n8][3]));
        }
    }
}

// ---------------------------------------------------------------------------
extern "C" void kernel_launch(void* const* d_in, const int* in_sizes, int n_in,
                              void* d_out, int out_size)
{
    const float* A     = (const float*)d_in[0];
    const float* x     = (const float*)d_in[1];
    const float* w     = (const float*)d_in[2];
    const float* theta = (const float*)d_in[3];
    float* out = (float*)d_out;

    cudaFuncSetAttribute(k1_gemm, cudaFuncAttributeMaxDynamicSharedMemorySize, SMEM_TOT);
    cudaFuncSetAttribute(k2_agg,  cudaFuncAttributeMaxDynamicSharedMemorySize, SMEM_TOT);

    k0_w<<<64, 256>>>(w, theta);
    k0_x<<<dim3(32, 16), 256>>>(x);
    k1_gemm<<<dim3(64, 16), 256, SMEM_TOT>>>(A);
    k2_agg<<<dim3(16, 16), 256, SMEM_TOT>>>(out);
}